// round 4
// baseline (speedup 1.0000x reference)
#include <cuda_runtime.h>
#include <cuda_bf16.h>
#include <cstdint>

// Rulebook sparse conv, legacy tensor-core path (harness targets sm_100 -> no tcgen05).
//   out[rules_out[k,r], :] += features[rules_in[k,r], :] @ weight[k, :, :]; out += bias.
// bf16x3 error-compensated: D = Ah*Bh + Ah*Bl + Al*Bh, fp32 accum (residual ~2^-18).
// R4: B fragments hoisted to registers (k constant per tile-range), 2-stage
// cp.async gather pipeline.

#define C_DIM    64
#define TILE_R   128
#define NTHREADS 128
#define MAXN     100000
#define MAXK     27
#define ROW_B    144   // padded row stride (bank-conflict-free STS/ldmatrix)

__device__ __nv_bfloat16 g_feat_hi[MAXN * C_DIM];
__device__ __nv_bfloat16 g_feat_lo[MAXN * C_DIM];
__device__ __nv_bfloat16 g_wt_hi[MAXK * C_DIM * C_DIM];   // [k][cin][cout]
__device__ __nv_bfloat16 g_wt_lo[MAXK * C_DIM * C_DIM];

// ---- smem layout ----
#define SMEM_OIDX   0                              // int[2][128]
#define SMEM_W_HI   1024                           // 64 x 144
#define SMEM_W_LO   (SMEM_W_HI + C_DIM * ROW_B)
#define SMEM_A      (SMEM_W_LO + C_DIM * ROW_B)    // 2 stages x (hi 128x144 + lo 128x144)
#define STAGE_HALF  (TILE_R * ROW_B)
#define STAGE_SZ    (2 * STAGE_HALF)
#define SMEM_BYTES  (SMEM_A + 2 * STAGE_SZ)        // 1024+18432+73728 = 93184

__device__ __forceinline__ uint32_t smem_u32(const void* p) {
    uint32_t a;
    asm("{ .reg .u64 t; cvta.to.shared.u64 t, %1; cvt.u32.u64 %0, t; }" : "=r"(a) : "l"(p));
    return a;
}
__device__ __forceinline__ void ldsm4(uint32_t* r, uint32_t addr) {
    asm volatile("ldmatrix.sync.aligned.m8n8.x4.shared.b16 {%0,%1,%2,%3}, [%4];"
                 : "=r"(r[0]), "=r"(r[1]), "=r"(r[2]), "=r"(r[3]) : "r"(addr));
}
__device__ __forceinline__ void ldsm4t(uint32_t* r, uint32_t addr) {
    asm volatile("ldmatrix.sync.aligned.m8n8.x4.trans.shared.b16 {%0,%1,%2,%3}, [%4];"
                 : "=r"(r[0]), "=r"(r[1]), "=r"(r[2]), "=r"(r[3]) : "r"(addr));
}
__device__ __forceinline__ void mma16816(float* c, const uint32_t* a, const uint32_t* b) {
    asm volatile("mma.sync.aligned.m16n8k16.row.col.f32.bf16.bf16.f32 "
                 "{%0,%1,%2,%3}, {%4,%5,%6,%7}, {%8,%9}, {%0,%1,%2,%3};"
                 : "+f"(c[0]), "+f"(c[1]), "+f"(c[2]), "+f"(c[3])
                 : "r"(a[0]), "r"(a[1]), "r"(a[2]), "r"(a[3]), "r"(b[0]), "r"(b[1]));
}
__device__ __forceinline__ void red_add_v2(float* addr, float x, float y) {
    asm volatile("red.global.add.v2.f32 [%0], {%1, %2};"
                 :: "l"(addr), "f"(x), "f"(y) : "memory");
}
__device__ __forceinline__ void cp_async16(uint32_t dst, const void* src) {
    asm volatile("cp.async.cg.shared.global [%0], [%1], 16;" :: "r"(dst), "l"(src) : "memory");
}
#define CP_COMMIT() asm volatile("cp.async.commit_group;" ::: "memory")
#define CP_WAIT1()  asm volatile("cp.async.wait_group 1;" ::: "memory")
#define CP_WAIT0()  asm volatile("cp.async.wait_group 0;" ::: "memory")

// ============================ prep kernels ============================

__global__ void prep_feat_kernel(const float* __restrict__ f, int count4) {
    int i = blockIdx.x * blockDim.x + threadIdx.x;
    if (i >= count4) return;
    float4 v = ((const float4*)f)[i];
    __nv_bfloat16 h0 = __float2bfloat16_rn(v.x), h1 = __float2bfloat16_rn(v.y);
    __nv_bfloat16 h2 = __float2bfloat16_rn(v.z), h3 = __float2bfloat16_rn(v.w);
    __nv_bfloat16 l0 = __float2bfloat16_rn(v.x - __bfloat162float(h0));
    __nv_bfloat16 l1 = __float2bfloat16_rn(v.y - __bfloat162float(h1));
    __nv_bfloat16 l2 = __float2bfloat16_rn(v.z - __bfloat162float(h2));
    __nv_bfloat16 l3 = __float2bfloat16_rn(v.w - __bfloat162float(h3));
    ((__nv_bfloat162*)g_feat_hi)[2 * i]     = __nv_bfloat162(h0, h1);
    ((__nv_bfloat162*)g_feat_hi)[2 * i + 1] = __nv_bfloat162(h2, h3);
    ((__nv_bfloat162*)g_feat_lo)[2 * i]     = __nv_bfloat162(l0, l1);
    ((__nv_bfloat162*)g_feat_lo)[2 * i + 1] = __nv_bfloat162(l2, l3);
}

__global__ void prep_wt_kernel(const float* __restrict__ w, int total) {
    int i = blockIdx.x * blockDim.x + threadIdx.x;
    if (i >= total) return;
    float x = w[i];
    __nv_bfloat16 h = __float2bfloat16_rn(x);
    g_wt_hi[i] = h;
    g_wt_lo[i] = __float2bfloat16_rn(x - __bfloat162float(h));
}

__global__ void bias_init_kernel(float* __restrict__ out, const float* __restrict__ bias, int total4) {
    int i = blockIdx.x * blockDim.x + threadIdx.x;
    if (i < total4) {
        const float4* b4 = (const float4*)bias;
        ((float4*)out)[i] = b4[i & (C_DIM / 4 - 1)];
    }
}

// ============================ main kernel ============================

__global__ void __launch_bounds__(NTHREADS, 2)
conv_mma_kernel(const int* __restrict__ rules_in,
                const int* __restrict__ rules_out,
                float* __restrict__ out,
                int n_rows, int tiles_per_k, int total_tiles, int tiles_per_cta)
{
    extern __shared__ char smem[];
    const uint32_t smem_base = smem_u32(smem);
    const int tid = threadIdx.x;
    const int wid = tid >> 5;
    const int lid = tid & 31;
    int* oidx_s = (int*)(smem + SMEM_OIDX);   // [2][128]

    const int tile0 = blockIdx.x * tiles_per_cta;
    if (tile0 >= total_tiles) return;
    int tileEnd = tile0 + tiles_per_cta;
    if (tileEnd > total_tiles) tileEnd = total_tiles;

    // ---- gather-issue helper (one rule per thread, 16B cp.async x16) ----
    auto issue_gather = [&](int t, int stage) {
        const int kt   = t / tiles_per_k;
        const int row0 = (t - kt * tiles_per_k) * TILE_R;
        const int gr   = row0 + tid;
        int in_idx = 0, out_idx = -1;
        if (gr < n_rows) {
            in_idx  = rules_in [(size_t)kt * n_rows + gr];
            out_idx = rules_out[(size_t)kt * n_rows + gr];
        }
        oidx_s[stage * TILE_R + tid] = out_idx;
        const char* sh = (const char*)(g_feat_hi + (size_t)in_idx * C_DIM);
        const char* sl = (const char*)(g_feat_lo + (size_t)in_idx * C_DIM);
        uint32_t dh = smem_base + SMEM_A + stage * STAGE_SZ + tid * ROW_B;
        uint32_t dl = dh + STAGE_HALF;
        #pragma unroll
        for (int j = 0; j < 8; j++) {
            cp_async16(dh + j * 16, sh + j * 16);
            cp_async16(dl + j * 16, sl + j * 16);
        }
        CP_COMMIT();
    };

    uint32_t Bh[4][4][4], Bl[4][4][4];   // [kc][nt16][reg] hoisted weight frags
    int cur_k = -1;

    issue_gather(tile0, 0);

    for (int t = tile0; t < tileEnd; t++) {
        const int s = (t - tile0) & 1;
        const int k = t / tiles_per_k;

        // ---- (re)load W[k] fragments into registers on k-change ----
        if (k != cur_k) {
            cur_k = k;
            __syncthreads();
            {
                const int r = tid & 63;
                const float4* src = (const float4*)(
                    ((tid < 64) ? g_wt_hi : g_wt_lo) + ((size_t)k * C_DIM + r) * C_DIM);
                char* dst = smem + ((tid < 64) ? SMEM_W_HI : SMEM_W_LO) + r * ROW_B;
                #pragma unroll
                for (int j = 0; j < 8; j++)
                    *(float4*)(dst + j * 16) = src[j];
            }
            __syncthreads();
            #pragma unroll
            for (int kc = 0; kc < 4; kc++) {
                const int brow = kc * 16 + (lid & 15);
                #pragma unroll
                for (int nt16 = 0; nt16 < 4; nt16++) {
                    uint32_t boff = brow * ROW_B + (nt16 * 16 + (lid >> 4) * 8) * 2;
                    ldsm4t(Bh[kc][nt16], smem_base + SMEM_W_HI + boff);
                    ldsm4t(Bl[kc][nt16], smem_base + SMEM_W_LO + boff);
                }
            }
        }

        // ---- prefetch next tile's gather into the other stage ----
        if (t + 1 < tileEnd) { issue_gather(t + 1, s ^ 1); CP_WAIT1(); }
        else                 { CP_WAIT0(); }
        __syncthreads();

        // ---- warp GEMM on stage s: 32 rows x 64 cols, bf16x3 ----
        float acc[2][8][4];
        #pragma unroll
        for (int mt = 0; mt < 2; mt++)
            #pragma unroll
            for (int nt = 0; nt < 8; nt++)
                #pragma unroll
                for (int e = 0; e < 4; e++) acc[mt][nt][e] = 0.f;

        const uint32_t a_hi = smem_base + SMEM_A + s * STAGE_SZ;
        const uint32_t a_lo = a_hi + STAGE_HALF;

        #pragma unroll
        for (int kc = 0; kc < 4; kc++) {
            uint32_t ah[2][4], al[2][4];
            #pragma unroll
            for (int mt = 0; mt < 2; mt++) {
                const int arow = wid * 32 + mt * 16 + (lid & 15);
                const uint32_t aoff = arow * ROW_B + (kc * 16 + (lid >> 4) * 8) * 2;
                ldsm4(ah[mt], a_hi + aoff);
                ldsm4(al[mt], a_lo + aoff);
            }
            #pragma unroll
            for (int mt = 0; mt < 2; mt++)
                #pragma unroll
                for (int nt16 = 0; nt16 < 4; nt16++) {
                    mma16816(acc[mt][2 * nt16],     ah[mt], &Bh[kc][nt16][0]);
                    mma16816(acc[mt][2 * nt16 + 1], ah[mt], &Bh[kc][nt16][2]);
                    mma16816(acc[mt][2 * nt16],     ah[mt], &Bl[kc][nt16][0]);
                    mma16816(acc[mt][2 * nt16 + 1], ah[mt], &Bl[kc][nt16][2]);
                    mma16816(acc[mt][2 * nt16],     al[mt], &Bh[kc][nt16][0]);
                    mma16816(acc[mt][2 * nt16 + 1], al[mt], &Bh[kc][nt16][2]);
                }
        }

        // ---- scatter: red.v2 per (row, col-pair) ----
        #pragma unroll
        for (int mt = 0; mt < 2; mt++) {
            const int r0  = wid * 32 + mt * 16 + (lid >> 2);
            const int oiA = oidx_s[s * TILE_R + r0];
            const int oiB = oidx_s[s * TILE_R + r0 + 8];
            const int c0  = (lid & 3) * 2;
            if (oiA >= 0) {
                float* dA = out + (size_t)oiA * C_DIM + c0;
                #pragma unroll
                for (int nt = 0; nt < 8; nt++)
                    red_add_v2(dA + nt * 8, acc[mt][nt][0], acc[mt][nt][1]);
            }
            if (oiB >= 0) {
                float* dB = out + (size_t)oiB * C_DIM + c0;
                #pragma unroll
                for (int nt = 0; nt < 8; nt++)
                    red_add_v2(dB + nt * 8, acc[mt][nt][2], acc[mt][nt][3]);
            }
        }
        __syncthreads();   // stage s + oidx reusable for prefetch at t+2
    }
}

// ============================ launch ============================

extern "C" void kernel_launch(void* const* d_in, const int* in_sizes, int n_in,
                              void* d_out, int out_size)
{
    const float* features  = (const float*)d_in[0];
    const float* weight    = (const float*)d_in[1];
    const float* bias      = (const float*)d_in[2];
    const int*   rules_in  = (const int*)d_in[3];
    const int*   rules_out = (const int*)d_in[4];

    const int n_rows = in_sizes[0] / C_DIM;
    const int K      = in_sizes[1] / (C_DIM * C_DIM);
    float* out = (float*)d_out;

    const int count4 = in_sizes[0] / 4;
    prep_feat_kernel<<<(count4 + 255) / 256, 256>>>(features, count4);
    const int wtot = K * C_DIM * C_DIM;
    prep_wt_kernel<<<(wtot + 255) / 256, 256>>>(weight, wtot);

    const int total4 = out_size / 4;
    bias_init_kernel<<<(total4 + 255) / 256, 256>>>(out, bias, total4);

    const int tiles_per_k   = (n_rows + TILE_R - 1) / TILE_R;
    const int total_tiles   = K * tiles_per_k;
    const int NCTA          = 296;   // 148 SMs x 2 resident
    const int tiles_per_cta = (total_tiles + NCTA - 1) / NCTA;

    cudaFuncSetAttribute(conv_mma_kernel,
                         cudaFuncAttributeMaxDynamicSharedMemorySize, SMEM_BYTES);
    conv_mma_kernel<<<NCTA, NTHREADS, SMEM_BYTES>>>(
        rules_in, rules_out, out, n_rows, tiles_per_k, total_tiles, tiles_per_cta);
}

// round 5
// speedup vs baseline: 1.1703x; 1.1703x over previous
#include <cuda_runtime.h>
#include <cuda_bf16.h>
#include <cstdint>

// Rulebook sparse conv, legacy tensor-core path (harness targets sm_100 -> no tcgen05).
//   out[rules_out[k,r], :] += features[rules_in[k,r], :] @ weight[k, :, :]; out += bias.
// bf16x3 error-compensated: D = Ah*Bh + Ah*Bl + Al*Bh, fp32 accum (residual ~2^-18).
// R5 = R3 + line-coalesced cooperative gather (8 lanes per feature row:
// 8 x 16B = one 128B line -> 4 wavefronts per warp LDG instead of ~32).

#define C_DIM    64
#define TILE_R   128
#define NTHREADS 128
#define MAXN     100000
#define MAXK     27
#define ROW_B    144   // padded smem row stride (conflict-free STS/ldmatrix)

__device__ __nv_bfloat16 g_feat_hi[MAXN * C_DIM];
__device__ __nv_bfloat16 g_feat_lo[MAXN * C_DIM];
__device__ __nv_bfloat16 g_wt_hi[MAXK * C_DIM * C_DIM];   // [k][cin][cout]
__device__ __nv_bfloat16 g_wt_lo[MAXK * C_DIM * C_DIM];

// ---- smem layout ----
#define SMEM_OIDX  0                              // int[128]
#define SMEM_INIDX 512                            // int[128]
#define SMEM_W_HI  1024                           // 64 x 144
#define SMEM_W_LO  (SMEM_W_HI + C_DIM * ROW_B)
#define SMEM_A_HI  (SMEM_W_LO + C_DIM * ROW_B)    // 128 x 144
#define SMEM_A_LO  (SMEM_A_HI + TILE_R * ROW_B)
#define SMEM_BYTES (SMEM_A_LO + TILE_R * ROW_B)   // 1024 + 18432 + 36864 = 56320

__device__ __forceinline__ uint32_t smem_u32(const void* p) {
    uint32_t a;
    asm("{ .reg .u64 t; cvta.to.shared.u64 t, %1; cvt.u32.u64 %0, t; }" : "=r"(a) : "l"(p));
    return a;
}
__device__ __forceinline__ void ldsm4(uint32_t* r, uint32_t addr) {
    asm volatile("ldmatrix.sync.aligned.m8n8.x4.shared.b16 {%0,%1,%2,%3}, [%4];"
                 : "=r"(r[0]), "=r"(r[1]), "=r"(r[2]), "=r"(r[3]) : "r"(addr));
}
__device__ __forceinline__ void ldsm4t(uint32_t* r, uint32_t addr) {
    asm volatile("ldmatrix.sync.aligned.m8n8.x4.trans.shared.b16 {%0,%1,%2,%3}, [%4];"
                 : "=r"(r[0]), "=r"(r[1]), "=r"(r[2]), "=r"(r[3]) : "r"(addr));
}
__device__ __forceinline__ void mma16816(float* c, const uint32_t* a, const uint32_t* b) {
    asm volatile("mma.sync.aligned.m16n8k16.row.col.f32.bf16.bf16.f32 "
                 "{%0,%1,%2,%3}, {%4,%5,%6,%7}, {%8,%9}, {%0,%1,%2,%3};"
                 : "+f"(c[0]), "+f"(c[1]), "+f"(c[2]), "+f"(c[3])
                 : "r"(a[0]), "r"(a[1]), "r"(a[2]), "r"(a[3]), "r"(b[0]), "r"(b[1]));
}
__device__ __forceinline__ void red_add_v2(float* addr, float x, float y) {
    asm volatile("red.global.add.v2.f32 [%0], {%1, %2};"
                 :: "l"(addr), "f"(x), "f"(y) : "memory");
}

// ============================ prep kernels ============================

__global__ void prep_feat_kernel(const float* __restrict__ f, int count4) {
    int i = blockIdx.x * blockDim.x + threadIdx.x;
    if (i >= count4) return;
    float4 v = ((const float4*)f)[i];
    __nv_bfloat16 h0 = __float2bfloat16_rn(v.x), h1 = __float2bfloat16_rn(v.y);
    __nv_bfloat16 h2 = __float2bfloat16_rn(v.z), h3 = __float2bfloat16_rn(v.w);
    __nv_bfloat16 l0 = __float2bfloat16_rn(v.x - __bfloat162float(h0));
    __nv_bfloat16 l1 = __float2bfloat16_rn(v.y - __bfloat162float(h1));
    __nv_bfloat16 l2 = __float2bfloat16_rn(v.z - __bfloat162float(h2));
    __nv_bfloat16 l3 = __float2bfloat16_rn(v.w - __bfloat162float(h3));
    ((__nv_bfloat162*)g_feat_hi)[2 * i]     = __nv_bfloat162(h0, h1);
    ((__nv_bfloat162*)g_feat_hi)[2 * i + 1] = __nv_bfloat162(h2, h3);
    ((__nv_bfloat162*)g_feat_lo)[2 * i]     = __nv_bfloat162(l0, l1);
    ((__nv_bfloat162*)g_feat_lo)[2 * i + 1] = __nv_bfloat162(l2, l3);
}

__global__ void prep_wt_kernel(const float* __restrict__ w, int total) {
    int i = blockIdx.x * blockDim.x + threadIdx.x;
    if (i >= total) return;
    float x = w[i];
    __nv_bfloat16 h = __float2bfloat16_rn(x);
    g_wt_hi[i] = h;
    g_wt_lo[i] = __float2bfloat16_rn(x - __bfloat162float(h));
}

__global__ void bias_init_kernel(float* __restrict__ out, const float* __restrict__ bias, int total4) {
    int i = blockIdx.x * blockDim.x + threadIdx.x;
    if (i < total4) {
        const float4* b4 = (const float4*)bias;
        ((float4*)out)[i] = b4[i & (C_DIM / 4 - 1)];
    }
}

// ============================ main kernel ============================

__global__ void __launch_bounds__(NTHREADS, 3)
conv_mma_kernel(const int* __restrict__ rules_in,
                const int* __restrict__ rules_out,
                float* __restrict__ out,
                int n_rows, int tiles_per_k, int total_tiles, int tiles_per_cta)
{
    extern __shared__ char smem[];
    const uint32_t smem_base = smem_u32(smem);
    const int tid = threadIdx.x;
    const int wid = tid >> 5;
    const int lid = tid & 31;
    int* oidx_s = (int*)(smem + SMEM_OIDX);
    int* inix_s = (int*)(smem + SMEM_INIDX);

    const int tile0 = blockIdx.x * tiles_per_cta;
    if (tile0 >= total_tiles) return;
    int tileEnd = tile0 + tiles_per_cta;
    if (tileEnd > total_tiles) tileEnd = total_tiles;
    int cur_k = -1;

    const int sub  = tid & 7;    // 16B chunk within a 128B row
    const int rloc = tid >> 3;   // row group base (0..15)

    for (int tile = tile0; tile < tileEnd; tile++) {
        const int k    = tile / tiles_per_k;
        const int row0 = (tile - k * tiles_per_k) * TILE_R;

        // ---- stage W[k] (hi+lo) on k-change ----
        if (k != cur_k) {
            cur_k = k;
            const int r = tid & 63;
            const float4* src = (const float4*)(
                ((tid < 64) ? g_wt_hi : g_wt_lo) + ((size_t)k * C_DIM + r) * C_DIM);
            char* dst = smem + ((tid < 64) ? SMEM_W_HI : SMEM_W_LO) + r * ROW_B;
            #pragma unroll
            for (int j = 0; j < 8; j++)
                *(float4*)(dst + j * 16) = src[j];
        }

        // ---- stage 1: rule indices (coalesced) ----
        {
            const int gr = row0 + tid;
            int in_idx = 0, out_idx = -1;
            if (gr < n_rows) {
                in_idx  = rules_in [(size_t)k * n_rows + gr];
                out_idx = rules_out[(size_t)k * n_rows + gr];
            }
            inix_s[tid] = in_idx;
            oidx_s[tid] = out_idx;
        }
        __syncthreads();

        // ---- stage 2: line-coalesced gather; 8 lanes cover one 128B row ----
        {
            #pragma unroll
            for (int j = 0; j < 8; j++) {
                const int row = rloc + 16 * j;
                const size_t in = (size_t)inix_s[row];
                const float4 vh = ((const float4*)(g_feat_hi + in * C_DIM))[sub];
                const float4 vl = ((const float4*)(g_feat_lo + in * C_DIM))[sub];
                *(float4*)(smem + SMEM_A_HI + row * ROW_B + sub * 16) = vh;
                *(float4*)(smem + SMEM_A_LO + row * ROW_B + sub * 16) = vl;
            }
        }
        __syncthreads();

        // ---- warp GEMM: 32 rows x 64 cols, K=64, bf16x3 ----
        float acc[2][8][4];
        #pragma unroll
        for (int mt = 0; mt < 2; mt++)
            #pragma unroll
            for (int nt = 0; nt < 8; nt++)
                #pragma unroll
                for (int e = 0; e < 4; e++) acc[mt][nt][e] = 0.f;

        #pragma unroll
        for (int kc = 0; kc < 4; kc++) {
            uint32_t ah[2][4], al[2][4];
            #pragma unroll
            for (int mt = 0; mt < 2; mt++) {
                const int arow = wid * 32 + mt * 16 + (lid & 15);
                const uint32_t aoff = arow * ROW_B + (kc * 16 + (lid >> 4) * 8) * 2;
                ldsm4(ah[mt], smem_base + SMEM_A_HI + aoff);
                ldsm4(al[mt], smem_base + SMEM_A_LO + aoff);
            }
            uint32_t bh[4][4], bl[4][4];
            #pragma unroll
            for (int nt16 = 0; nt16 < 4; nt16++) {
                const int brow = kc * 16 + (lid & 15);
                const uint32_t boff = brow * ROW_B + (nt16 * 16 + (lid >> 4) * 8) * 2;
                ldsm4t(bh[nt16], smem_base + SMEM_W_HI + boff);
                ldsm4t(bl[nt16], smem_base + SMEM_W_LO + boff);
            }
            #pragma unroll
            for (int mt = 0; mt < 2; mt++)
                #pragma unroll
                for (int nt16 = 0; nt16 < 4; nt16++) {
                    mma16816(acc[mt][2 * nt16],     ah[mt], &bh[nt16][0]);
                    mma16816(acc[mt][2 * nt16 + 1], ah[mt], &bh[nt16][2]);
                    mma16816(acc[mt][2 * nt16],     ah[mt], &bl[nt16][0]);
                    mma16816(acc[mt][2 * nt16 + 1], ah[mt], &bl[nt16][2]);
                    mma16816(acc[mt][2 * nt16],     al[mt], &bh[nt16][0]);
                    mma16816(acc[mt][2 * nt16 + 1], al[mt], &bh[nt16][2]);
                }
        }

        // ---- scatter: red.v2 per (row, col-pair) ----
        #pragma unroll
        for (int mt = 0; mt < 2; mt++) {
            const int r0  = wid * 32 + mt * 16 + (lid >> 2);
            const int oiA = oidx_s[r0];
            const int oiB = oidx_s[r0 + 8];
            const int c0  = (lid & 3) * 2;
            if (oiA >= 0) {
                float* dA = out + (size_t)oiA * C_DIM + c0;
                #pragma unroll
                for (int nt = 0; nt < 8; nt++)
                    red_add_v2(dA + nt * 8, acc[mt][nt][0], acc[mt][nt][1]);
            }
            if (oiB >= 0) {
                float* dB = out + (size_t)oiB * C_DIM + c0;
                #pragma unroll
                for (int nt = 0; nt < 8; nt++)
                    red_add_v2(dB + nt * 8, acc[mt][nt][2], acc[mt][nt][3]);
            }
        }
        __syncthreads();   // smem reusable next tile
    }
}

// ============================ launch ============================

extern "C" void kernel_launch(void* const* d_in, const int* in_sizes, int n_in,
                              void* d_out, int out_size)
{
    const float* features  = (const float*)d_in[0];
    const float* weight    = (const float*)d_in[1];
    const float* bias      = (const float*)d_in[2];
    const int*   rules_in  = (const int*)d_in[3];
    const int*   rules_out = (const int*)d_in[4];

    const int n_rows = in_sizes[0] / C_DIM;
    const int K      = in_sizes[1] / (C_DIM * C_DIM);
    float* out = (float*)d_out;

    const int count4 = in_sizes[0] / 4;
    prep_feat_kernel<<<(count4 + 255) / 256, 256>>>(features, count4);
    const int wtot = K * C_DIM * C_DIM;
    prep_wt_kernel<<<(wtot + 255) / 256, 256>>>(weight, wtot);

    const int total4 = out_size / 4;
    bias_init_kernel<<<(total4 + 255) / 256, 256>>>(out, bias, total4);

    const int tiles_per_k   = (n_rows + TILE_R - 1) / TILE_R;
    const int total_tiles   = K * tiles_per_k;
    const int NCTA          = 444;   // 148 SMs x 3 resident
    const int tiles_per_cta = (total_tiles + NCTA - 1) / NCTA;

    cudaFuncSetAttribute(conv_mma_kernel,
                         cudaFuncAttributeMaxDynamicSharedMemorySize, SMEM_BYTES);
    conv_mma_kernel<<<NCTA, NTHREADS, SMEM_BYTES>>>(
        rules_in, rules_out, out, n_rows, tiles_per_k, total_tiles, tiles_per_cta);
}

// round 7
// speedup vs baseline: 1.2788x; 1.0927x over previous
#include <cuda_runtime.h>
#include <cuda_bf16.h>
#include <cstdint>

// Rulebook sparse conv, legacy tensor-core path (harness targets sm_100 -> no tcgen05).
//   out[rules_out[k,r], :] += features[rules_in[k,r], :] @ weight[k, :, :]; out += bias.
// bf16x3 error-compensated: D = Ah*Bh + Ah*Bl + Al*Bh, fp32 accum (residual ~2^-18).
// R7 = R6 resubmit (prior round died to container infra failure, not the kernel):
// R5 coalesced gather + smem B, 256 threads (16 rows/warp, low regs),
// 2-stage cp.async pipeline overlapping gather(t+1) with MMA/scatter(t).

#define C_DIM    64
#define TILE_R   128
#define NTHREADS 256
#define MAXN     100000
#define MAXK     27
#define ROW_B    144   // padded smem row stride (conflict-free STS/ldmatrix)

__device__ __nv_bfloat16 g_feat_hi[MAXN * C_DIM];
__device__ __nv_bfloat16 g_feat_lo[MAXN * C_DIM];
__device__ __nv_bfloat16 g_wt_hi[MAXK * C_DIM * C_DIM];   // [k][cin][cout]
__device__ __nv_bfloat16 g_wt_lo[MAXK * C_DIM * C_DIM];

// ---- smem layout ----
#define SMEM_OIDX   0                               // int[2][128]
#define SMEM_W_HI   1024                            // 64 x 144
#define SMEM_W_LO   (SMEM_W_HI + C_DIM * ROW_B)
#define SMEM_A      (SMEM_W_LO + C_DIM * ROW_B)     // 2 stages x (hi + lo), 128 x 144 each
#define STAGE_HALF  (TILE_R * ROW_B)
#define STAGE_SZ    (2 * STAGE_HALF)
#define SMEM_BYTES  (SMEM_A + 2 * STAGE_SZ)         // 1024 + 18432 + 73728 = 93184

__device__ __forceinline__ uint32_t smem_u32(const void* p) {
    uint32_t a;
    asm("{ .reg .u64 t; cvta.to.shared.u64 t, %1; cvt.u32.u64 %0, t; }" : "=r"(a) : "l"(p));
    return a;
}
__device__ __forceinline__ void ldsm4(uint32_t* r, uint32_t addr) {
    asm volatile("ldmatrix.sync.aligned.m8n8.x4.shared.b16 {%0,%1,%2,%3}, [%4];"
                 : "=r"(r[0]), "=r"(r[1]), "=r"(r[2]), "=r"(r[3]) : "r"(addr));
}
__device__ __forceinline__ void ldsm4t(uint32_t* r, uint32_t addr) {
    asm volatile("ldmatrix.sync.aligned.m8n8.x4.trans.shared.b16 {%0,%1,%2,%3}, [%4];"
                 : "=r"(r[0]), "=r"(r[1]), "=r"(r[2]), "=r"(r[3]) : "r"(addr));
}
__device__ __forceinline__ void mma16816(float* c, const uint32_t* a, const uint32_t* b) {
    asm volatile("mma.sync.aligned.m16n8k16.row.col.f32.bf16.bf16.f32 "
                 "{%0,%1,%2,%3}, {%4,%5,%6,%7}, {%8,%9}, {%0,%1,%2,%3};"
                 : "+f"(c[0]), "+f"(c[1]), "+f"(c[2]), "+f"(c[3])
                 : "r"(a[0]), "r"(a[1]), "r"(a[2]), "r"(a[3]), "r"(b[0]), "r"(b[1]));
}
__device__ __forceinline__ void red_add_v2(float* addr, float x, float y) {
    asm volatile("red.global.add.v2.f32 [%0], {%1, %2};"
                 :: "l"(addr), "f"(x), "f"(y) : "memory");
}
__device__ __forceinline__ void cp_async16(uint32_t dst, const void* src) {
    asm volatile("cp.async.cg.shared.global [%0], [%1], 16;" :: "r"(dst), "l"(src) : "memory");
}
#define CP_COMMIT() asm volatile("cp.async.commit_group;" ::: "memory")
#define CP_WAIT1()  asm volatile("cp.async.wait_group 1;" ::: "memory")
#define CP_WAIT0()  asm volatile("cp.async.wait_group 0;" ::: "memory")

// ============================ prep kernels ============================

__global__ void prep_feat_kernel(const float* __restrict__ f, int count4) {
    int i = blockIdx.x * blockDim.x + threadIdx.x;
    if (i >= count4) return;
    float4 v = ((const float4*)f)[i];
    __nv_bfloat16 h0 = __float2bfloat16_rn(v.x), h1 = __float2bfloat16_rn(v.y);
    __nv_bfloat16 h2 = __float2bfloat16_rn(v.z), h3 = __float2bfloat16_rn(v.w);
    __nv_bfloat16 l0 = __float2bfloat16_rn(v.x - __bfloat162float(h0));
    __nv_bfloat16 l1 = __float2bfloat16_rn(v.y - __bfloat162float(h1));
    __nv_bfloat16 l2 = __float2bfloat16_rn(v.z - __bfloat162float(h2));
    __nv_bfloat16 l3 = __float2bfloat16_rn(v.w - __bfloat162float(h3));
    ((__nv_bfloat162*)g_feat_hi)[2 * i]     = __nv_bfloat162(h0, h1);
    ((__nv_bfloat162*)g_feat_hi)[2 * i + 1] = __nv_bfloat162(h2, h3);
    ((__nv_bfloat162*)g_feat_lo)[2 * i]     = __nv_bfloat162(l0, l1);
    ((__nv_bfloat162*)g_feat_lo)[2 * i + 1] = __nv_bfloat162(l2, l3);
}

__global__ void prep_wt_kernel(const float* __restrict__ w, int total) {
    int i = blockIdx.x * blockDim.x + threadIdx.x;
    if (i >= total) return;
    float x = w[i];
    __nv_bfloat16 h = __float2bfloat16_rn(x);
    g_wt_hi[i] = h;
    g_wt_lo[i] = __float2bfloat16_rn(x - __bfloat162float(h));
}

__global__ void bias_init_kernel(float* __restrict__ out, const float* __restrict__ bias, int total4) {
    int i = blockIdx.x * blockDim.x + threadIdx.x;
    if (i < total4) {
        const float4* b4 = (const float4*)bias;
        ((float4*)out)[i] = b4[i & (C_DIM / 4 - 1)];
    }
}

// ============================ main kernel ============================

__global__ void __launch_bounds__(NTHREADS, 2)
conv_mma_kernel(const int* __restrict__ rules_in,
                const int* __restrict__ rules_out,
                float* __restrict__ out,
                int n_rows, int tiles_per_k, int total_tiles, int tiles_per_cta)
{
    extern __shared__ char smem[];
    const uint32_t smem_base = smem_u32(smem);
    const int tid = threadIdx.x;
    const int wid = tid >> 5;
    const int lid = tid & 31;
    int* oidx_s = (int*)(smem + SMEM_OIDX);   // [2][128]

    const int tile0 = blockIdx.x * tiles_per_cta;
    if (tile0 >= total_tiles) return;
    int tileEnd = tile0 + tiles_per_cta;
    if (tileEnd > total_tiles) tileEnd = total_tiles;

    const int sub  = tid & 7;    // 16B chunk within a 128B row
    const int rloc = tid >> 3;   // 0..31: base row within each 32-row group

    // one rule per feature row; 8 lanes cooperate per row (broadcast idx LDG,
    // then one full 128B line of hi + one of lo via cp.async)
    auto issue_gather = [&](int t, int stage) {
        const int kt   = t / tiles_per_k;
        const int row0 = (t - kt * tiles_per_k) * TILE_R;
        if (tid < TILE_R) {
            const int gr = row0 + tid;
            oidx_s[stage * TILE_R + tid] = (gr < n_rows)
                ? rules_out[(size_t)kt * n_rows + gr] : -1;
        }
        const uint32_t st_hi = smem_base + SMEM_A + stage * STAGE_SZ;
        const uint32_t st_lo = st_hi + STAGE_HALF;
        #pragma unroll
        for (int j = 0; j < 4; j++) {
            const int row = rloc + 32 * j;
            const int gr  = row0 + row;
            const size_t in = (gr < n_rows)
                ? (size_t)rules_in[(size_t)kt * n_rows + gr] : 0;
            cp_async16(st_hi + row * ROW_B + sub * 16,
                       (const char*)(g_feat_hi + in * C_DIM) + sub * 16);
            cp_async16(st_lo + row * ROW_B + sub * 16,
                       (const char*)(g_feat_lo + in * C_DIM) + sub * 16);
        }
        CP_COMMIT();
    };

    int cur_k = -1;
    issue_gather(tile0, 0);

    for (int t = tile0; t < tileEnd; t++) {
        const int s = (t - tile0) & 1;
        const int k = t / tiles_per_k;

        // ---- stage W[k] (hi+lo) on k-change (prev iter's sync protects old W) ----
        if (k != cur_k) {
            cur_k = k;
            if (tid < 128) {
                const int r = tid & 63;
                const float4* src = (const float4*)(
                    ((tid < 64) ? g_wt_hi : g_wt_lo) + ((size_t)k * C_DIM + r) * C_DIM);
                char* dst = smem + ((tid < 64) ? SMEM_W_HI : SMEM_W_LO) + r * ROW_B;
                #pragma unroll
                for (int j = 0; j < 8; j++)
                    *(float4*)(dst + j * 16) = src[j];
            }
        }

        // ---- prefetch next tile into the other stage, wait for this one ----
        if (t + 1 < tileEnd) { issue_gather(t + 1, s ^ 1); CP_WAIT1(); }
        else                 { CP_WAIT0(); }
        __syncthreads();

        const uint32_t a_hi = smem_base + SMEM_A + s * STAGE_SZ;
        const uint32_t a_lo = a_hi + STAGE_HALF;

        // ---- warp GEMM: 16 rows x 64 cols, K=64, bf16x3 ----
        float acc[8][4];
        #pragma unroll
        for (int nt = 0; nt < 8; nt++)
            #pragma unroll
            for (int e = 0; e < 4; e++) acc[nt][e] = 0.f;

        #pragma unroll
        for (int kc = 0; kc < 4; kc++) {
            uint32_t ah[4], al[4];
            {
                const int arow = wid * 16 + (lid & 15);
                const uint32_t aoff = arow * ROW_B + (kc * 16 + (lid >> 4) * 8) * 2;
                ldsm4(ah, a_hi + aoff);
                ldsm4(al, a_lo + aoff);
            }
            uint32_t bh[4][4], bl[4][4];
            #pragma unroll
            for (int nt16 = 0; nt16 < 4; nt16++) {
                const int brow = kc * 16 + (lid & 15);
                const uint32_t boff = brow * ROW_B + (nt16 * 16 + (lid >> 4) * 8) * 2;
                ldsm4t(bh[nt16], smem_base + SMEM_W_HI + boff);
                ldsm4t(bl[nt16], smem_base + SMEM_W_LO + boff);
            }
            #pragma unroll
            for (int nt16 = 0; nt16 < 4; nt16++) {
                mma16816(acc[2 * nt16],     ah, &bh[nt16][0]);
                mma16816(acc[2 * nt16 + 1], ah, &bh[nt16][2]);
                mma16816(acc[2 * nt16],     ah, &bl[nt16][0]);
                mma16816(acc[2 * nt16 + 1], ah, &bl[nt16][2]);
                mma16816(acc[2 * nt16],     al, &bh[nt16][0]);
                mma16816(acc[2 * nt16 + 1], al, &bh[nt16][2]);
            }
        }

        // ---- scatter: red.v2 per (row, col-pair) ----
        {
            const int r0  = wid * 16 + (lid >> 2);
            const int oiA = oidx_s[s * TILE_R + r0];
            const int oiB = oidx_s[s * TILE_R + r0 + 8];
            const int c0  = (lid & 3) * 2;
            if (oiA >= 0) {
                float* dA = out + (size_t)oiA * C_DIM + c0;
                #pragma unroll
                for (int nt = 0; nt < 8; nt++)
                    red_add_v2(dA + nt * 8, acc[nt][0], acc[nt][1]);
            }
            if (oiB >= 0) {
                float* dB = out + (size_t)oiB * C_DIM + c0;
                #pragma unroll
                for (int nt = 0; nt < 8; nt++)
                    red_add_v2(dB + nt * 8, acc[nt][2], acc[nt][3]);
            }
        }
        __syncthreads();   // stage s + its oidx free for reuse at t+2
    }
}

// ============================ launch ============================

extern "C" void kernel_launch(void* const* d_in, const int* in_sizes, int n_in,
                              void* d_out, int out_size)
{
    const float* features  = (const float*)d_in[0];
    const float* weight    = (const float*)d_in[1];
    const float* bias      = (const float*)d_in[2];
    const int*   rules_in  = (const int*)d_in[3];
    const int*   rules_out = (const int*)d_in[4];

    const int n_rows = in_sizes[0] / C_DIM;
    const int K      = in_sizes[1] / (C_DIM * C_DIM);
    float* out = (float*)d_out;

    const int count4 = in_sizes[0] / 4;
    prep_feat_kernel<<<(count4 + 255) / 256, 256>>>(features, count4);
    const int wtot = K * C_DIM * C_DIM;
    prep_wt_kernel<<<(wtot + 255) / 256, 256>>>(weight, wtot);

    const int total4 = out_size / 4;
    bias_init_kernel<<<(total4 + 255) / 256, 256>>>(out, bias, total4);

    const int tiles_per_k   = (n_rows + TILE_R - 1) / TILE_R;
    const int total_tiles   = K * tiles_per_k;
    const int NCTA          = 296;   // 148 SMs x 2 resident (smem-limited)
    const int tiles_per_cta = (total_tiles + NCTA - 1) / NCTA;

    cudaFuncSetAttribute(conv_mma_kernel,
                         cudaFuncAttributeMaxDynamicSharedMemorySize, SMEM_BYTES);
    conv_mma_kernel<<<NCTA, NTHREADS, SMEM_BYTES>>>(
        rules_in, rules_out, out, n_rows, tiles_per_k, total_tiles, tiles_per_cta);
}

// round 10
// speedup vs baseline: 1.4726x; 1.1516x over previous
#include <cuda_runtime.h>
#include <cuda_bf16.h>
#include <cstdint>

// Rulebook sparse conv, legacy tensor-core path (harness targets sm_100 -> no tcgen05).
//   out[rules_out[k,r], :] += features[rules_in[k,r], :] @ weight[k, :, :]; out += bias.
// bf16x3 error-compensated: D = Ah*Bh + Ah*Bl + Al*Bh, fp32 accum (residual ~2^-18).
// R9 = R8 resubmit (two infra container failures; R6->R7 precedent: identical
// kernel passed on retry). Barrier-free warp-private pipeline: each warp owns
// 16 rows/tile, gathers them itself (line-coalesced, idx via shfl), double-
// buffers in warp-private smem, per-warp cp.async wait. __syncthreads only on
// k-change (W restage, ~1 per CTA).

#define C_DIM    64
#define TILE_R   128
#define NTHREADS 256
#define NWARP    8
#define MAXN     100000
#define MAXK     27
#define ROW_B    144   // padded smem row stride (conflict-free STS/ldmatrix)

__device__ __nv_bfloat16 g_feat_hi[MAXN * C_DIM];
__device__ __nv_bfloat16 g_feat_lo[MAXN * C_DIM];
__device__ __nv_bfloat16 g_wt_hi[MAXK * C_DIM * C_DIM];   // [k][cin][cout]
__device__ __nv_bfloat16 g_wt_lo[MAXK * C_DIM * C_DIM];

// ---- smem layout ----
#define SMEM_W_HI   0
#define SMEM_W_LO   (SMEM_W_HI + C_DIM * ROW_B)
#define SMEM_A      (SMEM_W_LO + C_DIM * ROW_B)
#define PW_HALF     (16 * ROW_B)          // 2304 B (hi or lo block)
#define PW_STAGE    (2 * PW_HALF)         // 4608 B
#define PW_BLOCK    (2 * PW_STAGE)        // 9216 B per warp
#define SMEM_BYTES  (SMEM_A + NWARP * PW_BLOCK)   // 18432 + 73728 = 92160

__device__ __forceinline__ uint32_t smem_u32(const void* p) {
    uint32_t a;
    asm("{ .reg .u64 t; cvta.to.shared.u64 t, %1; cvt.u32.u64 %0, t; }" : "=r"(a) : "l"(p));
    return a;
}
__device__ __forceinline__ void ldsm4(uint32_t* r, uint32_t addr) {
    asm volatile("ldmatrix.sync.aligned.m8n8.x4.shared.b16 {%0,%1,%2,%3}, [%4];"
                 : "=r"(r[0]), "=r"(r[1]), "=r"(r[2]), "=r"(r[3]) : "r"(addr));
}
__device__ __forceinline__ void ldsm4t(uint32_t* r, uint32_t addr) {
    asm volatile("ldmatrix.sync.aligned.m8n8.x4.trans.shared.b16 {%0,%1,%2,%3}, [%4];"
                 : "=r"(r[0]), "=r"(r[1]), "=r"(r[2]), "=r"(r[3]) : "r"(addr));
}
__device__ __forceinline__ void mma16816(float* c, const uint32_t* a, const uint32_t* b) {
    asm volatile("mma.sync.aligned.m16n8k16.row.col.f32.bf16.bf16.f32 "
                 "{%0,%1,%2,%3}, {%4,%5,%6,%7}, {%8,%9}, {%0,%1,%2,%3};"
                 : "+f"(c[0]), "+f"(c[1]), "+f"(c[2]), "+f"(c[3])
                 : "r"(a[0]), "r"(a[1]), "r"(a[2]), "r"(a[3]), "r"(b[0]), "r"(b[1]));
}
__device__ __forceinline__ void red_add_v2(float* addr, float x, float y) {
    asm volatile("red.global.add.v2.f32 [%0], {%1, %2};"
                 :: "l"(addr), "f"(x), "f"(y) : "memory");
}
__device__ __forceinline__ void cp_async16(uint32_t dst, const void* src) {
    asm volatile("cp.async.cg.shared.global [%0], [%1], 16;" :: "r"(dst), "l"(src) : "memory");
}
#define CP_COMMIT() asm volatile("cp.async.commit_group;" ::: "memory")
#define CP_WAIT1()  asm volatile("cp.async.wait_group 1;" ::: "memory")
#define CP_WAIT0()  asm volatile("cp.async.wait_group 0;" ::: "memory")

// ============================ prep kernels ============================

__global__ void prep_feat_kernel(const float* __restrict__ f, int count4) {
    int i = blockIdx.x * blockDim.x + threadIdx.x;
    if (i >= count4) return;
    float4 v = ((const float4*)f)[i];
    __nv_bfloat16 h0 = __float2bfloat16_rn(v.x), h1 = __float2bfloat16_rn(v.y);
    __nv_bfloat16 h2 = __float2bfloat16_rn(v.z), h3 = __float2bfloat16_rn(v.w);
    __nv_bfloat16 l0 = __float2bfloat16_rn(v.x - __bfloat162float(h0));
    __nv_bfloat16 l1 = __float2bfloat16_rn(v.y - __bfloat162float(h1));
    __nv_bfloat16 l2 = __float2bfloat16_rn(v.z - __bfloat162float(h2));
    __nv_bfloat16 l3 = __float2bfloat16_rn(v.w - __bfloat162float(h3));
    ((__nv_bfloat162*)g_feat_hi)[2 * i]     = __nv_bfloat162(h0, h1);
    ((__nv_bfloat162*)g_feat_hi)[2 * i + 1] = __nv_bfloat162(h2, h3);
    ((__nv_bfloat162*)g_feat_lo)[2 * i]     = __nv_bfloat162(l0, l1);
    ((__nv_bfloat162*)g_feat_lo)[2 * i + 1] = __nv_bfloat162(l2, l3);
}

__global__ void prep_wt_kernel(const float* __restrict__ w, int total) {
    int i = blockIdx.x * blockDim.x + threadIdx.x;
    if (i >= total) return;
    float x = w[i];
    __nv_bfloat16 h = __float2bfloat16_rn(x);
    g_wt_hi[i] = h;
    g_wt_lo[i] = __float2bfloat16_rn(x - __bfloat162float(h));
}

__global__ void bias_init_kernel(float* __restrict__ out, const float* __restrict__ bias, int total4) {
    int i = blockIdx.x * blockDim.x + threadIdx.x;
    if (i < total4) {
        const float4* b4 = (const float4*)bias;
        ((float4*)out)[i] = b4[i & (C_DIM / 4 - 1)];
    }
}

// ============================ main kernel ============================

__global__ void __launch_bounds__(NTHREADS, 2)
conv_mma_kernel(const int* __restrict__ rules_in,
                const int* __restrict__ rules_out,
                float* __restrict__ out,
                int n_rows, int tiles_per_k, int total_tiles, int tiles_per_cta)
{
    extern __shared__ char smem[];
    const uint32_t smem_base = smem_u32(smem);
    const int tid = threadIdx.x;
    const int wid = tid >> 5;
    const int lid = tid & 31;

    const int tile0 = blockIdx.x * tiles_per_cta;
    if (tile0 >= total_tiles) return;
    int tileEnd = tile0 + tiles_per_cta;
    if (tileEnd > total_tiles) tileEnd = total_tiles;

    const uint32_t warp_a = smem_base + SMEM_A + wid * PW_BLOCK;
    const int      sub16  = (lid & 7) * 16;   // 16B chunk within a 128B row
    const int      rquad  = lid >> 3;         // 0..3: row offset within a 4-row op

    // per-warp gather of this warp's 16 rows; returns idx register:
    // lanes 0-15 hold in_idx(row=lane), lanes 16-31 hold out_idx(row=lane-16)
    auto issue_gather = [&](int t, int stage) -> int {
        const int kt   = t / tiles_per_k;
        const int row0 = (t - kt * tiles_per_k) * TILE_R + wid * 16;
        const int rr   = row0 + (lid & 15);
        int var;
        if (lid < 16)
            var = (rr < n_rows) ? rules_in [(size_t)kt * n_rows + rr] : 0;
        else
            var = (rr < n_rows) ? rules_out[(size_t)kt * n_rows + rr] : -1;

        const uint32_t st_hi = warp_a + stage * PW_STAGE;
        const uint32_t st_lo = st_hi + PW_HALF;
        #pragma unroll
        for (int g = 0; g < 4; g++) {
            const int row = g * 4 + rquad;                       // 0..15
            const size_t in = (size_t)__shfl_sync(0xFFFFFFFFu, var, row);
            cp_async16(st_hi + row * ROW_B + sub16,
                       (const char*)(g_feat_hi + in * C_DIM) + sub16);
            cp_async16(st_lo + row * ROW_B + sub16,
                       (const char*)(g_feat_lo + in * C_DIM) + sub16);
        }
        CP_COMMIT();
        return var;
    };

    // ---- initial W stage for this CTA's first k ----
    int cur_k = tile0 / tiles_per_k;
    {
        if (tid < 128) {
            const int r = tid & 63;
            const float4* src = (const float4*)(
                ((tid < 64) ? g_wt_hi : g_wt_lo) + ((size_t)cur_k * C_DIM + r) * C_DIM);
            char* dst = smem + ((tid < 64) ? SMEM_W_HI : SMEM_W_LO) + r * ROW_B;
            #pragma unroll
            for (int j = 0; j < 8; j++)
                *(float4*)(dst + j * 16) = src[j];
        }
        __syncthreads();
    }

    int vidx[2];
    vidx[0] = issue_gather(tile0, 0);

    for (int t = tile0; t < tileEnd; t++) {
        const int s  = (t - tile0) & 1;
        const int kt = t / tiles_per_k;

        // ---- k-change: restage shared W (CTA-uniform branch; rare) ----
        if (kt != cur_k) {
            cur_k = kt;
            __syncthreads();                 // everyone done reading old W
            if (tid < 128) {
                const int r = tid & 63;
                const float4* src = (const float4*)(
                    ((tid < 64) ? g_wt_hi : g_wt_lo) + ((size_t)kt * C_DIM + r) * C_DIM);
                char* dst = smem + ((tid < 64) ? SMEM_W_HI : SMEM_W_LO) + r * ROW_B;
                #pragma unroll
                for (int j = 0; j < 8; j++)
                    *(float4*)(dst + j * 16) = src[j];
            }
            __syncthreads();                 // new W visible
        }

        // ---- per-warp prefetch of t+1 into the other private stage ----
        if (t + 1 < tileEnd) { vidx[s ^ 1] = issue_gather(t + 1, s ^ 1); CP_WAIT1(); }
        else                 { CP_WAIT0(); }
        // no barrier: stage s is private to this warp, its cp.async group drained

        const uint32_t a_hi = warp_a + s * PW_STAGE;
        const uint32_t a_lo = a_hi + PW_HALF;

        // ---- warp GEMM: 16 rows x 64 cols, K=64, bf16x3 ----
        float acc[8][4];
        #pragma unroll
        for (int nt = 0; nt < 8; nt++)
            #pragma unroll
            for (int e = 0; e < 4; e++) acc[nt][e] = 0.f;

        #pragma unroll
        for (int kc = 0; kc < 4; kc++) {
            uint32_t ah[4], al[4];
            {
                const uint32_t aoff = (lid & 15) * ROW_B + kc * 32 + (lid >> 4) * 16;
                ldsm4(ah, a_hi + aoff);
                ldsm4(al, a_lo + aoff);
            }
            uint32_t bh[4][4], bl[4][4];
            #pragma unroll
            for (int nt16 = 0; nt16 < 4; nt16++) {
                const int brow = kc * 16 + (lid & 15);
                const uint32_t boff = brow * ROW_B + (nt16 * 16 + (lid >> 4) * 8) * 2;
                ldsm4t(bh[nt16], smem_base + SMEM_W_HI + boff);
                ldsm4t(bl[nt16], smem_base + SMEM_W_LO + boff);
            }
            #pragma unroll
            for (int nt16 = 0; nt16 < 4; nt16++) {
                mma16816(acc[2 * nt16],     ah, &bh[nt16][0]);
                mma16816(acc[2 * nt16 + 1], ah, &bh[nt16][2]);
                mma16816(acc[2 * nt16],     ah, &bl[nt16][0]);
                mma16816(acc[2 * nt16 + 1], ah, &bl[nt16][2]);
                mma16816(acc[2 * nt16],     al, &bh[nt16][0]);
                mma16816(acc[2 * nt16 + 1], al, &bh[nt16][2]);
            }
        }

        // ---- scatter: red.v2 per (row, col-pair); out_idx via shfl ----
        {
            const int r0  = lid >> 2;                       // 0..7
            const int oiA = __shfl_sync(0xFFFFFFFFu, vidx[s], 16 + r0);
            const int oiB = __shfl_sync(0xFFFFFFFFu, vidx[s], 16 + r0 + 8);
            const int c0  = (lid & 3) * 2;
            if (oiA >= 0) {
                float* dA = out + (size_t)oiA * C_DIM + c0;
                #pragma unroll
                for (int nt = 0; nt < 8; nt++)
                    red_add_v2(dA + nt * 8, acc[nt][0], acc[nt][1]);
            }
            if (oiB >= 0) {
                float* dB = out + (size_t)oiB * C_DIM + c0;
                #pragma unroll
                for (int nt = 0; nt < 8; nt++)
                    red_add_v2(dB + nt * 8, acc[nt][2], acc[nt][3]);
            }
        }
        // no barrier: next iteration only touches this warp's own stages
    }
}

// ============================ launch ============================

extern "C" void kernel_launch(void* const* d_in, const int* in_sizes, int n_in,
                              void* d_out, int out_size)
{
    const float* features  = (const float*)d_in[0];
    const float* weight    = (const float*)d_in[1];
    const float* bias      = (const float*)d_in[2];
    const int*   rules_in  = (const int*)d_in[3];
    const int*   rules_out = (const int*)d_in[4];

    const int n_rows = in_sizes[0] / C_DIM;
    const int K      = in_sizes[1] / (C_DIM * C_DIM);
    float* out = (float*)d_out;

    const int count4 = in_sizes[0] / 4;
    prep_feat_kernel<<<(count4 + 255) / 256, 256>>>(features, count4);
    const int wtot = K * C_DIM * C_DIM;
    prep_wt_kernel<<<(wtot + 255) / 256, 256>>>(weight, wtot);

    const int total4 = out_size / 4;
    bias_init_kernel<<<(total4 + 255) / 256, 256>>>(out, bias, total4);

    const int tiles_per_k   = (n_rows + TILE_R - 1) / TILE_R;
    const int total_tiles   = K * tiles_per_k;
    const int NCTA          = 296;   // 148 SMs x 2 resident (smem-limited)
    const int tiles_per_cta = (total_tiles + NCTA - 1) / NCTA;

    cudaFuncSetAttribute(conv_mma_kernel,
                         cudaFuncAttributeMaxDynamicSharedMemorySize, SMEM_BYTES);
    conv_mma_kernel<<<NCTA, NTHREADS, SMEM_BYTES>>>(
        rules_in, rules_out, out, n_rows, tiles_per_k, total_tiles, tiles_per_cta);
}

// round 12
// speedup vs baseline: 1.4755x; 1.0019x over previous
#include <cuda_runtime.h>
#include <cuda_bf16.h>
#include <cstdint>

// Rulebook sparse conv, legacy tensor-core path (harness targets sm_100 -> no tcgen05).
//   out[rules_out[k,r], :] += features[rules_in[k,r], :] @ weight[k, :, :]; out += bias.
// bf16x3 error-compensated: D = Ah*Bh + Ah*Bl + Al*Bh, fp32 accum (residual ~2^-18).
// R12 = R11 resubmit (broker flake pattern: every first-submit of a new kernel
// since R6 fails, verbatim retry passes — R6->R7, R8->R10 precedents).
// Barrier-free warp-private pipeline at 10 warps/CTA (20 warps/SM @ 2 CTAs),
// fused prep kernel, hoisted scatter-index shfls.

#define C_DIM    64
#define TILE_R   160            // NWARP * 16
#define NTHREADS 320
#define NWARP    10
#define MAXN     100000
#define MAXK     27
#define ROW_B    144   // padded smem row stride (conflict-free STS/ldmatrix)

__device__ __nv_bfloat16 g_feat_hi[MAXN * C_DIM];
__device__ __nv_bfloat16 g_feat_lo[MAXN * C_DIM];
__device__ __nv_bfloat16 g_wt_hi[MAXK * C_DIM * C_DIM];   // [k][cin][cout]
__device__ __nv_bfloat16 g_wt_lo[MAXK * C_DIM * C_DIM];

// ---- smem layout ----
#define SMEM_W_HI   0
#define SMEM_W_LO   (SMEM_W_HI + C_DIM * ROW_B)
#define SMEM_A      (SMEM_W_LO + C_DIM * ROW_B)
#define PW_HALF     (16 * ROW_B)          // 2304 B (hi or lo block)
#define PW_STAGE    (2 * PW_HALF)         // 4608 B
#define PW_BLOCK    (2 * PW_STAGE)        // 9216 B per warp
#define SMEM_BYTES  (SMEM_A + NWARP * PW_BLOCK)   // 18432 + 92160 = 110592

__device__ __forceinline__ uint32_t smem_u32(const void* p) {
    uint32_t a;
    asm("{ .reg .u64 t; cvta.to.shared.u64 t, %1; cvt.u32.u64 %0, t; }" : "=r"(a) : "l"(p));
    return a;
}
__device__ __forceinline__ void ldsm4(uint32_t* r, uint32_t addr) {
    asm volatile("ldmatrix.sync.aligned.m8n8.x4.shared.b16 {%0,%1,%2,%3}, [%4];"
                 : "=r"(r[0]), "=r"(r[1]), "=r"(r[2]), "=r"(r[3]) : "r"(addr));
}
__device__ __forceinline__ void ldsm4t(uint32_t* r, uint32_t addr) {
    asm volatile("ldmatrix.sync.aligned.m8n8.x4.trans.shared.b16 {%0,%1,%2,%3}, [%4];"
                 : "=r"(r[0]), "=r"(r[1]), "=r"(r[2]), "=r"(r[3]) : "r"(addr));
}
__device__ __forceinline__ void mma16816(float* c, const uint32_t* a, const uint32_t* b) {
    asm volatile("mma.sync.aligned.m16n8k16.row.col.f32.bf16.bf16.f32 "
                 "{%0,%1,%2,%3}, {%4,%5,%6,%7}, {%8,%9}, {%0,%1,%2,%3};"
                 : "+f"(c[0]), "+f"(c[1]), "+f"(c[2]), "+f"(c[3])
                 : "r"(a[0]), "r"(a[1]), "r"(a[2]), "r"(a[3]), "r"(b[0]), "r"(b[1]));
}
__device__ __forceinline__ void red_add_v2(float* addr, float x, float y) {
    asm volatile("red.global.add.v2.f32 [%0], {%1, %2};"
                 :: "l"(addr), "f"(x), "f"(y) : "memory");
}
__device__ __forceinline__ void cp_async16(uint32_t dst, const void* src) {
    asm volatile("cp.async.cg.shared.global [%0], [%1], 16;" :: "r"(dst), "l"(src) : "memory");
}
#define CP_COMMIT() asm volatile("cp.async.commit_group;" ::: "memory")
#define CP_WAIT1()  asm volatile("cp.async.wait_group 1;" ::: "memory")
#define CP_WAIT0()  asm volatile("cp.async.wait_group 0;" ::: "memory")

// ===================== fused prep kernel =====================
// One launch: bias broadcast into out, feature hi/lo split, weight hi/lo
// split. Independent index spaces, branch by range.

__global__ void prep_all_kernel(const float* __restrict__ f,   int count4,
                                const float* __restrict__ w,   int wtot,
                                const float* __restrict__ bias,
                                float* __restrict__ out,       int total4)
{
    const int i = blockIdx.x * blockDim.x + threadIdx.x;

    if (i < total4) {
        const float4* b4 = (const float4*)bias;
        ((float4*)out)[i] = b4[i & (C_DIM / 4 - 1)];
    }
    if (i < count4) {
        float4 v = ((const float4*)f)[i];
        __nv_bfloat16 h0 = __float2bfloat16_rn(v.x), h1 = __float2bfloat16_rn(v.y);
        __nv_bfloat16 h2 = __float2bfloat16_rn(v.z), h3 = __float2bfloat16_rn(v.w);
        __nv_bfloat16 l0 = __float2bfloat16_rn(v.x - __bfloat162float(h0));
        __nv_bfloat16 l1 = __float2bfloat16_rn(v.y - __bfloat162float(h1));
        __nv_bfloat16 l2 = __float2bfloat16_rn(v.z - __bfloat162float(h2));
        __nv_bfloat16 l3 = __float2bfloat16_rn(v.w - __bfloat162float(h3));
        ((__nv_bfloat162*)g_feat_hi)[2 * i]     = __nv_bfloat162(h0, h1);
        ((__nv_bfloat162*)g_feat_hi)[2 * i + 1] = __nv_bfloat162(h2, h3);
        ((__nv_bfloat162*)g_feat_lo)[2 * i]     = __nv_bfloat162(l0, l1);
        ((__nv_bfloat162*)g_feat_lo)[2 * i + 1] = __nv_bfloat162(l2, l3);
    }
    if (i < wtot) {
        float x = w[i];
        __nv_bfloat16 h = __float2bfloat16_rn(x);
        g_wt_hi[i] = h;
        g_wt_lo[i] = __float2bfloat16_rn(x - __bfloat162float(h));
    }
}

// ============================ main kernel ============================

__global__ void __launch_bounds__(NTHREADS, 2)
conv_mma_kernel(const int* __restrict__ rules_in,
                const int* __restrict__ rules_out,
                float* __restrict__ out,
                int n_rows, int tiles_per_k, int total_tiles, int tiles_per_cta)
{
    extern __shared__ char smem[];
    const uint32_t smem_base = smem_u32(smem);
    const int tid = threadIdx.x;
    const int wid = tid >> 5;
    const int lid = tid & 31;

    const int tile0 = blockIdx.x * tiles_per_cta;
    if (tile0 >= total_tiles) return;
    int tileEnd = tile0 + tiles_per_cta;
    if (tileEnd > total_tiles) tileEnd = total_tiles;

    const uint32_t warp_a = smem_base + SMEM_A + wid * PW_BLOCK;
    const int      sub16  = (lid & 7) * 16;   // 16B chunk within a 128B row
    const int      rquad  = lid >> 3;         // 0..3: row offset within a 4-row op

    // per-warp gather of this warp's 16 rows; returns idx register:
    // lanes 0-15 hold in_idx(row=lane), lanes 16-31 hold out_idx(row=lane-16)
    auto issue_gather = [&](int t, int stage) -> int {
        const int kt   = t / tiles_per_k;
        const int row0 = (t - kt * tiles_per_k) * TILE_R + wid * 16;
        const int rr   = row0 + (lid & 15);
        int var;
        if (lid < 16)
            var = (rr < n_rows) ? rules_in [(size_t)kt * n_rows + rr] : 0;
        else
            var = (rr < n_rows) ? rules_out[(size_t)kt * n_rows + rr] : -1;

        const uint32_t st_hi = warp_a + stage * PW_STAGE;
        const uint32_t st_lo = st_hi + PW_HALF;
        #pragma unroll
        for (int g = 0; g < 4; g++) {
            const int row = g * 4 + rquad;                       // 0..15
            const size_t in = (size_t)__shfl_sync(0xFFFFFFFFu, var, row);
            cp_async16(st_hi + row * ROW_B + sub16,
                       (const char*)(g_feat_hi + in * C_DIM) + sub16);
            cp_async16(st_lo + row * ROW_B + sub16,
                       (const char*)(g_feat_lo + in * C_DIM) + sub16);
        }
        CP_COMMIT();
        return var;
    };

    // ---- initial W stage for this CTA's first k ----
    int cur_k = tile0 / tiles_per_k;
    {
        if (tid < 128) {
            const int r = tid & 63;
            const float4* src = (const float4*)(
                ((tid < 64) ? g_wt_hi : g_wt_lo) + ((size_t)cur_k * C_DIM + r) * C_DIM);
            char* dst = smem + ((tid < 64) ? SMEM_W_HI : SMEM_W_LO) + r * ROW_B;
            #pragma unroll
            for (int j = 0; j < 8; j++)
                *(float4*)(dst + j * 16) = src[j];
        }
        __syncthreads();
    }

    int vidx[2];
    vidx[0] = issue_gather(tile0, 0);

    for (int t = tile0; t < tileEnd; t++) {
        const int s  = (t - tile0) & 1;
        const int kt = t / tiles_per_k;

        // ---- k-change: restage shared W (CTA-uniform branch; rare) ----
        if (kt != cur_k) {
            cur_k = kt;
            __syncthreads();                 // everyone done reading old W
            if (tid < 128) {
                const int r = tid & 63;
                const float4* src = (const float4*)(
                    ((tid < 64) ? g_wt_hi : g_wt_lo) + ((size_t)kt * C_DIM + r) * C_DIM);
                char* dst = smem + ((tid < 64) ? SMEM_W_HI : SMEM_W_LO) + r * ROW_B;
                #pragma unroll
                for (int j = 0; j < 8; j++)
                    *(float4*)(dst + j * 16) = src[j];
            }
            __syncthreads();                 // new W visible
        }

        // ---- per-warp prefetch of t+1 into the other private stage ----
        if (t + 1 < tileEnd) { vidx[s ^ 1] = issue_gather(t + 1, s ^ 1); CP_WAIT1(); }
        else                 { CP_WAIT0(); }
        // no barrier: stage s is private to this warp, its cp.async group drained

        // ---- hoist scatter indices off the acc->RED critical path ----
        const int r0  = lid >> 2;                                      // 0..7
        const int oiA = __shfl_sync(0xFFFFFFFFu, vidx[s], 16 + r0);
        const int oiB = __shfl_sync(0xFFFFFFFFu, vidx[s], 16 + r0 + 8);

        const uint32_t a_hi = warp_a + s * PW_STAGE;
        const uint32_t a_lo = a_hi + PW_HALF;

        // ---- warp GEMM: 16 rows x 64 cols, K=64, bf16x3 ----
        float acc[8][4];
        #pragma unroll
        for (int nt = 0; nt < 8; nt++)
            #pragma unroll
            for (int e = 0; e < 4; e++) acc[nt][e] = 0.f;

        #pragma unroll
        for (int kc = 0; kc < 4; kc++) {
            uint32_t ah[4], al[4];
            {
                const uint32_t aoff = (lid & 15) * ROW_B + kc * 32 + (lid >> 4) * 16;
                ldsm4(ah, a_hi + aoff);
                ldsm4(al, a_lo + aoff);
            }
            uint32_t bh[4][4], bl[4][4];
            #pragma unroll
            for (int nt16 = 0; nt16 < 4; nt16++) {
                const int brow = kc * 16 + (lid & 15);
                const uint32_t boff = brow * ROW_B + (nt16 * 16 + (lid >> 4) * 8) * 2;
                ldsm4t(bh[nt16], smem_base + SMEM_W_HI + boff);
                ldsm4t(bl[nt16], smem_base + SMEM_W_LO + boff);
            }
            #pragma unroll
            for (int nt16 = 0; nt16 < 4; nt16++) {
                mma16816(acc[2 * nt16],     ah, &bh[nt16][0]);
                mma16816(acc[2 * nt16 + 1], ah, &bh[nt16][2]);
                mma16816(acc[2 * nt16],     ah, &bl[nt16][0]);
                mma16816(acc[2 * nt16 + 1], ah, &bl[nt16][2]);
                mma16816(acc[2 * nt16],     al, &bh[nt16][0]);
                mma16816(acc[2 * nt16 + 1], al, &bh[nt16][2]);
            }
        }

        // ---- scatter: red.v2 per (row, col-pair) ----
        {
            const int c0 = (lid & 3) * 2;
            if (oiA >= 0) {
                float* dA = out + (size_t)oiA * C_DIM + c0;
                #pragma unroll
                for (int nt = 0; nt < 8; nt++)
                    red_add_v2(dA + nt * 8, acc[nt][0], acc[nt][1]);
            }
            if (oiB >= 0) {
                float* dB = out + (size_t)oiB * C_DIM + c0;
                #pragma unroll
                for (int nt = 0; nt < 8; nt++)
                    red_add_v2(dB + nt * 8, acc[nt][2], acc[nt][3]);
            }
        }
        // no barrier: next iteration only touches this warp's own stages
    }
}

// ============================ launch ============================

extern "C" void kernel_launch(void* const* d_in, const int* in_sizes, int n_in,
                              void* d_out, int out_size)
{
    const float* features  = (const float*)d_in[0];
    const float* weight    = (const float*)d_in[1];
    const float* bias      = (const float*)d_in[2];
    const int*   rules_in  = (const int*)d_in[3];
    const int*   rules_out = (const int*)d_in[4];

    const int n_rows = in_sizes[0] / C_DIM;
    const int K      = in_sizes[1] / (C_DIM * C_DIM);
    float* out = (float*)d_out;

    const int count4 = in_sizes[0] / 4;
    const int wtot   = K * C_DIM * C_DIM;
    const int total4 = out_size / 4;
    int prep_n = total4 > count4 ? total4 : count4;
    if (wtot > prep_n) prep_n = wtot;
    prep_all_kernel<<<(prep_n + 255) / 256, 256>>>(features, count4, weight, wtot,
                                                   bias, out, total4);

    const int tiles_per_k   = (n_rows + TILE_R - 1) / TILE_R;
    const int total_tiles   = K * tiles_per_k;
    const int NCTA          = 296;   // 148 SMs x 2 resident
    const int tiles_per_cta = (total_tiles + NCTA - 1) / NCTA;

    cudaFuncSetAttribute(conv_mma_kernel,
                         cudaFuncAttributeMaxDynamicSharedMemorySize, SMEM_BYTES);
    conv_mma_kernel<<<NCTA, NTHREADS, SMEM_BYTES>>>(
        rules_in, rules_out, out, n_rows, tiles_per_k, total_tiles, tiles_per_cta);
}

// round 13
// speedup vs baseline: 1.5620x; 1.0587x over previous
#include <cuda_runtime.h>
#include <cuda_bf16.h>
#include <cstdint>

// Rulebook sparse conv, legacy tensor-core path (harness targets sm_100 -> no tcgen05).
//   out[rules_out[k,r], :] += features[rules_in[k,r], :] @ weight[k, :, :]; out += bias.
// bf16x3 error-compensated: D = Ah*Bh + Ah*Bl + Al*Bh, fp32 accum (residual ~2^-18).
// R13: 3-stage warp-private pipeline (prefetch distance 2 -> 2x gather-latency
// tolerance) + XOR-swizzled 128B smem rows (no padding; frees smem for stage 3).
// 8 warps/CTA, 2 CTAs/SM. Fused prep, hoisted scatter shfls, barrier-free loop.

#define C_DIM    64
#define TILE_R   128            // NWARP * 16
#define NTHREADS 256
#define NWARP    8
#define MAXN     100000
#define MAXK     27
#define ROW_B    128            // 128B rows, XOR swizzle (conflict-free)

// swizzled byte offset of 16B chunk c16 in row: (c16 ^ (row&7)) * 16
#define SWZ_OFF(row, c16)  (((uint32_t)(row) * ROW_B) + ((((c16) ^ ((row) & 7)) & 7) << 4))

__device__ __nv_bfloat16 g_feat_hi[MAXN * C_DIM];
__device__ __nv_bfloat16 g_feat_lo[MAXN * C_DIM];
__device__ __nv_bfloat16 g_wt_hi[MAXK * C_DIM * C_DIM];   // [k][cin][cout]
__device__ __nv_bfloat16 g_wt_lo[MAXK * C_DIM * C_DIM];

// ---- smem layout ----
#define SMEM_W_HI   0                              // 64 x 128
#define SMEM_W_LO   (SMEM_W_HI + C_DIM * ROW_B)    // 64 x 128
#define SMEM_A      (SMEM_W_LO + C_DIM * ROW_B)    // per-warp 3-stage blocks
#define PW_HALF     (16 * ROW_B)          // 2048 B (hi or lo block)
#define PW_STAGE    (2 * PW_HALF)         // 4096 B
#define NSTAGE      3
#define PW_BLOCK    (NSTAGE * PW_STAGE)   // 12288 B per warp
#define SMEM_BYTES  (SMEM_A + NWARP * PW_BLOCK)   // 16384 + 98304 = 114688

__device__ __forceinline__ uint32_t smem_u32(const void* p) {
    uint32_t a;
    asm("{ .reg .u64 t; cvta.to.shared.u64 t, %1; cvt.u32.u64 %0, t; }" : "=r"(a) : "l"(p));
    return a;
}
__device__ __forceinline__ void ldsm4(uint32_t* r, uint32_t addr) {
    asm volatile("ldmatrix.sync.aligned.m8n8.x4.shared.b16 {%0,%1,%2,%3}, [%4];"
                 : "=r"(r[0]), "=r"(r[1]), "=r"(r[2]), "=r"(r[3]) : "r"(addr));
}
__device__ __forceinline__ void ldsm4t(uint32_t* r, uint32_t addr) {
    asm volatile("ldmatrix.sync.aligned.m8n8.x4.trans.shared.b16 {%0,%1,%2,%3}, [%4];"
                 : "=r"(r[0]), "=r"(r[1]), "=r"(r[2]), "=r"(r[3]) : "r"(addr));
}
__device__ __forceinline__ void mma16816(float* c, const uint32_t* a, const uint32_t* b) {
    asm volatile("mma.sync.aligned.m16n8k16.row.col.f32.bf16.bf16.f32 "
                 "{%0,%1,%2,%3}, {%4,%5,%6,%7}, {%8,%9}, {%0,%1,%2,%3};"
                 : "+f"(c[0]), "+f"(c[1]), "+f"(c[2]), "+f"(c[3])
                 : "r"(a[0]), "r"(a[1]), "r"(a[2]), "r"(a[3]), "r"(b[0]), "r"(b[1]));
}
__device__ __forceinline__ void red_add_v2(float* addr, float x, float y) {
    asm volatile("red.global.add.v2.f32 [%0], {%1, %2};"
                 :: "l"(addr), "f"(x), "f"(y) : "memory");
}
__device__ __forceinline__ void cp_async16(uint32_t dst, const void* src) {
    asm volatile("cp.async.cg.shared.global [%0], [%1], 16;" :: "r"(dst), "l"(src) : "memory");
}
#define CP_COMMIT() asm volatile("cp.async.commit_group;" ::: "memory")
#define CP_WAIT2()  asm volatile("cp.async.wait_group 2;" ::: "memory")
#define CP_WAIT1()  asm volatile("cp.async.wait_group 1;" ::: "memory")
#define CP_WAIT0()  asm volatile("cp.async.wait_group 0;" ::: "memory")

// ===================== fused prep kernel =====================

__global__ void prep_all_kernel(const float* __restrict__ f,   int count4,
                                const float* __restrict__ w,   int wtot,
                                const float* __restrict__ bias,
                                float* __restrict__ out,       int total4)
{
    const int i = blockIdx.x * blockDim.x + threadIdx.x;

    if (i < total4) {
        const float4* b4 = (const float4*)bias;
        ((float4*)out)[i] = b4[i & (C_DIM / 4 - 1)];
    }
    if (i < count4) {
        float4 v = ((const float4*)f)[i];
        __nv_bfloat16 h0 = __float2bfloat16_rn(v.x), h1 = __float2bfloat16_rn(v.y);
        __nv_bfloat16 h2 = __float2bfloat16_rn(v.z), h3 = __float2bfloat16_rn(v.w);
        __nv_bfloat16 l0 = __float2bfloat16_rn(v.x - __bfloat162float(h0));
        __nv_bfloat16 l1 = __float2bfloat16_rn(v.y - __bfloat162float(h1));
        __nv_bfloat16 l2 = __float2bfloat16_rn(v.z - __bfloat162float(h2));
        __nv_bfloat16 l3 = __float2bfloat16_rn(v.w - __bfloat162float(h3));
        ((__nv_bfloat162*)g_feat_hi)[2 * i]     = __nv_bfloat162(h0, h1);
        ((__nv_bfloat162*)g_feat_hi)[2 * i + 1] = __nv_bfloat162(h2, h3);
        ((__nv_bfloat162*)g_feat_lo)[2 * i]     = __nv_bfloat162(l0, l1);
        ((__nv_bfloat162*)g_feat_lo)[2 * i + 1] = __nv_bfloat162(l2, l3);
    }
    if (i < wtot) {
        float x = w[i];
        __nv_bfloat16 h = __float2bfloat16_rn(x);
        g_wt_hi[i] = h;
        g_wt_lo[i] = __float2bfloat16_rn(x - __bfloat162float(h));
    }
}

// ============================ main kernel ============================

__global__ void __launch_bounds__(NTHREADS, 2)
conv_mma_kernel(const int* __restrict__ rules_in,
                const int* __restrict__ rules_out,
                float* __restrict__ out,
                int n_rows, int tiles_per_k, int total_tiles, int tiles_per_cta)
{
    extern __shared__ char smem[];
    const uint32_t smem_base = smem_u32(smem);
    const int tid = threadIdx.x;
    const int wid = tid >> 5;
    const int lid = tid & 31;

    const int tile0 = blockIdx.x * tiles_per_cta;
    if (tile0 >= total_tiles) return;
    int tileEnd = tile0 + tiles_per_cta;
    if (tileEnd > total_tiles) tileEnd = total_tiles;

    const uint32_t warp_a = smem_base + SMEM_A + wid * PW_BLOCK;
    const int      sub    = lid & 7;     // 16B chunk index within a 128B row
    const int      rquad  = lid >> 3;    // 0..3: row offset within a 4-row op

    // per-warp gather of this warp's 16 rows; returns idx register:
    // lanes 0-15 hold in_idx(row=lane), lanes 16-31 hold out_idx(row=lane-16)
    auto issue_gather = [&](int t, int stage) -> int {
        const int kt   = t / tiles_per_k;
        const int row0 = (t - kt * tiles_per_k) * TILE_R + wid * 16;
        const int rr   = row0 + (lid & 15);
        int var;
        if (lid < 16)
            var = (rr < n_rows) ? rules_in [(size_t)kt * n_rows + rr] : 0;
        else
            var = (rr < n_rows) ? rules_out[(size_t)kt * n_rows + rr] : -1;

        const uint32_t st_hi = warp_a + stage * PW_STAGE;
        const uint32_t st_lo = st_hi + PW_HALF;
        #pragma unroll
        for (int g = 0; g < 4; g++) {
            const int row = g * 4 + rquad;                       // 0..15
            const size_t in = (size_t)__shfl_sync(0xFFFFFFFFu, var, row);
            const uint32_t off = SWZ_OFF(row, sub);
            cp_async16(st_hi + off, (const char*)(g_feat_hi + in * C_DIM) + sub * 16);
            cp_async16(st_lo + off, (const char*)(g_feat_lo + in * C_DIM) + sub * 16);
        }
        CP_COMMIT();
        return var;
    };

    // ---- W staging helper (swizzled 128B rows), tid<128 participates ----
    auto stage_w = [&](int k) {
        if (tid < 128) {
            const int r = tid & 63;
            const float4* src = (const float4*)(
                ((tid < 64) ? g_wt_hi : g_wt_lo) + ((size_t)k * C_DIM + r) * C_DIM);
            const uint32_t dst = smem_base + ((tid < 64) ? SMEM_W_HI : SMEM_W_LO);
            #pragma unroll
            for (int j = 0; j < 8; j++)
                *(float4*)((char*)smem + (dst - smem_base) + SWZ_OFF(r, j)) = src[j];
        }
    };

    // ---- initial W stage for this CTA's first k ----
    int cur_k = tile0 / tiles_per_k;
    stage_w(cur_k);
    __syncthreads();

    int vidx[NSTAGE];
    vidx[0] = issue_gather(tile0, 0);
    if (tile0 + 1 < tileEnd) vidx[1] = issue_gather(tile0 + 1, 1);

    int s = 0;
    for (int t = tile0; t < tileEnd; t++) {
        const int kt = t / tiles_per_k;

        // ---- k-change: restage shared W (CTA-uniform branch; rare) ----
        if (kt != cur_k) {
            cur_k = kt;
            __syncthreads();                 // everyone done reading old W
            stage_w(kt);
            __syncthreads();                 // new W visible
        }

        // ---- prefetch t+2 into stage s+2; wait for tile t's group ----
        int s2 = s + 2; if (s2 >= NSTAGE) s2 -= NSTAGE;
        if (t + 2 < tileEnd)      { vidx[s2] = issue_gather(t + 2, s2); CP_WAIT2(); }
        else if (t + 1 < tileEnd) { CP_WAIT1(); }
        else                      { CP_WAIT0(); }
        // no barrier: stage s is private to this warp, its cp.async group drained

        // ---- hoist scatter indices off the acc->RED critical path ----
        const int r0  = lid >> 2;                                      // 0..7
        const int oiA = __shfl_sync(0xFFFFFFFFu, vidx[s], 16 + r0);
        const int oiB = __shfl_sync(0xFFFFFFFFu, vidx[s], 16 + r0 + 8);

        const uint32_t a_hi = warp_a + s * PW_STAGE;
        const uint32_t a_lo = a_hi + PW_HALF;

        // ---- warp GEMM: 16 rows x 64 cols, K=64, bf16x3 ----
        float acc[8][4];
        #pragma unroll
        for (int nt = 0; nt < 8; nt++)
            #pragma unroll
            for (int e = 0; e < 4; e++) acc[nt][e] = 0.f;

        #pragma unroll
        for (int kc = 0; kc < 4; kc++) {
            uint32_t ah[4], al[4];
            {
                const int arow = lid & 15;
                const uint32_t aoff = SWZ_OFF(arow, kc * 2 + (lid >> 4));
                ldsm4(ah, a_hi + aoff);
                ldsm4(al, a_lo + aoff);
            }
            uint32_t bh[4][4], bl[4][4];
            #pragma unroll
            for (int nt16 = 0; nt16 < 4; nt16++) {
                const int brow = kc * 16 + (lid & 15);
                const uint32_t boff = SWZ_OFF(brow, nt16 * 2 + (lid >> 4));
                ldsm4t(bh[nt16], smem_base + SMEM_W_HI + boff);
                ldsm4t(bl[nt16], smem_base + SMEM_W_LO + boff);
            }
            #pragma unroll
            for (int nt16 = 0; nt16 < 4; nt16++) {
                mma16816(acc[2 * nt16],     ah, &bh[nt16][0]);
                mma16816(acc[2 * nt16 + 1], ah, &bh[nt16][2]);
                mma16816(acc[2 * nt16],     ah, &bl[nt16][0]);
                mma16816(acc[2 * nt16 + 1], ah, &bl[nt16][2]);
                mma16816(acc[2 * nt16],     al, &bh[nt16][0]);
                mma16816(acc[2 * nt16 + 1], al, &bh[nt16][2]);
            }
        }

        // ---- scatter: red.v2 per (row, col-pair) ----
        {
            const int c0 = (lid & 3) * 2;
            if (oiA >= 0) {
                float* dA = out + (size_t)oiA * C_DIM + c0;
                #pragma unroll
                for (int nt = 0; nt < 8; nt++)
                    red_add_v2(dA + nt * 8, acc[nt][0], acc[nt][1]);
            }
            if (oiB >= 0) {
                float* dB = out + (size_t)oiB * C_DIM + c0;
                #pragma unroll
                for (int nt = 0; nt < 8; nt++)
                    red_add_v2(dB + nt * 8, acc[nt][2], acc[nt][3]);
            }
        }

        s = (s == NSTAGE - 1) ? 0 : s + 1;
        // no barrier: next iteration only touches this warp's own stages
    }
}

// ============================ launch ============================

extern "C" void kernel_launch(void* const* d_in, const int* in_sizes, int n_in,
                              void* d_out, int out_size)
{
    const float* features  = (const float*)d_in[0];
    const float* weight    = (const float*)d_in[1];
    const float* bias      = (const float*)d_in[2];
    const int*   rules_in  = (const int*)d_in[3];
    const int*   rules_out = (const int*)d_in[4];

    const int n_rows = in_sizes[0] / C_DIM;
    const int K      = in_sizes[1] / (C_DIM * C_DIM);
    float* out = (float*)d_out;

    const int count4 = in_sizes[0] / 4;
    const int wtot   = K * C_DIM * C_DIM;
    const int total4 = out_size / 4;
    int prep_n = total4 > count4 ? total4 : count4;
    if (wtot > prep_n) prep_n = wtot;
    prep_all_kernel<<<(prep_n + 255) / 256, 256>>>(features, count4, weight, wtot,
                                                   bias, out, total4);

    const int tiles_per_k   = (n_rows + TILE_R - 1) / TILE_R;
    const int total_tiles   = K * tiles_per_k;
    const int NCTA          = 296;   // 148 SMs x 2 resident
    const int tiles_per_cta = (total_tiles + NCTA - 1) / NCTA;

    cudaFuncSetAttribute(conv_mma_kernel,
                         cudaFuncAttributeMaxDynamicSharedMemorySize, SMEM_BYTES);
    conv_mma_kernel<<<NCTA, NTHREADS, SMEM_BYTES>>>(
        rules_in, rules_out, out, n_rows, tiles_per_k, total_tiles, tiles_per_cta);
}